// round 4
// baseline (speedup 1.0000x reference)
#include <cuda_runtime.h>
#include <math.h>
#include <float.h>

#define NB    8192      // batch
#define ND    128       // feature dim of z
#define NITEM 16384     // interaction vector length
#define NHID  32
#define NTOPK 10
#define FTEMP 0.1f
#define FNEGINF -9e9f

// ---------------- scratch (device globals; no runtime allocation) ----------
__device__ float  g_sim[(size_t)NB * NB];     // 256 MB similarity matrix
__device__ float  g_inv[NB];                  // 1/row-norm of t
__device__ float  g_alpha[NB];
__device__ float  g_nz[(size_t)NB * ND];      // neighbor_z
__device__ int    g_maxlen;
__device__ double g_part[4096];               // per-block loss partials

// ---------------- K0: max(real_len) ----------------------------------------
__global__ void k_maxlen(const int* __restrict__ real_len) {
    __shared__ int s[1024];
    int tid = threadIdx.x;
    int m = 0;
    for (int i = tid; i < NB; i += 1024) m = max(m, real_len[i]);
    s[tid] = m; __syncthreads();
    for (int o = 512; o; o >>= 1) {
        if (tid < o) s[tid] = max(s[tid], s[tid + o]);
        __syncthreads();
    }
    if (tid == 0) g_maxlen = s[0];
}

// ---------------- K1: alpha[b] (tiny MLP) -----------------------------------
__global__ void k_alpha(const int* __restrict__ real_len,
                        const float* __restrict__ W1, const float* __restrict__ b1,
                        const float* __restrict__ W2, const float* __restrict__ b2) {
    int b = blockIdx.x * blockDim.x + threadIdx.x;
    if (b >= NB) return;
    float ml = fmaxf((float)g_maxlen, 1.0f);
    float sp = 1.0f - (float)real_len[b] / ml;
    float acc = 0.f;
#pragma unroll
    for (int j = 0; j < NHID; j++) {
        float h = fmaxf(sp * W1[j] + b1[j], 0.f);
        acc += h * W2[j];
    }
    acc += b2[0];
    g_alpha[b] = 1.0f / (1.0f + expf(-acc));
}

// ---------------- K2: inverse row norms of t --------------------------------
// Two-level accumulation here too (chunked partials are already per-thread,
// 64 elems each -> fine).
__global__ void k_invnorm(const float* __restrict__ t) {
    int r = blockIdx.x;
    __shared__ float s[256];
    const float* row = t + (size_t)r * NITEM;
    float a = 0.f;
    for (int j = threadIdx.x; j < NITEM; j += 256) { float v = row[j]; a = fmaf(v, v, a); }
    s[threadIdx.x] = a; __syncthreads();
    for (int o = 128; o; o >>= 1) {
        if (threadIdx.x < o) s[threadIdx.x] += s[threadIdx.x + o];
        __syncthreads();
    }
    if (threadIdx.x == 0) {
        float n = sqrtf(s[0]);
        g_inv[r] = 1.0f / fmaxf(n, 1e-12f);
    }
}

// ---------------- K3: symmetric fp32 GEMM: sim = (t t^T) * inv_i * inv_j ----
// 128x128 tile per CTA, 256 threads, 8x8 microtile, BK=16, double buffered.
// Two-level accumulation: block accumulator folded into main every 256 k's.
// This cuts sequential-accumulation rounding noise ~15x (sigma ~1.2e-7 in sim
// units, below the rank-10/11 top-k gap) so top-k membership matches the
// reference's fp32 result.
// Only upper-triangular tile pairs computed; result mirrored.
__global__ void __launch_bounds__(256) k_gemm(const float* __restrict__ t) {
    int bx = blockIdx.x, by = blockIdx.y;   // bx = col tile, by = row tile
    if (bx < by) return;

    __shared__ float As[2][16][132];
    __shared__ float Bs[2][16][132];

    int tid = threadIdx.x;
    int ty = tid >> 4, tx = tid & 15;

    const size_t rowA0 = (size_t)by * 128;
    const size_t rowB0 = (size_t)bx * 128;

    float acc[8][8];    // main accumulator
    float accb[8][8];   // block accumulator (folded every 256 k)
#pragma unroll
    for (int i = 0; i < 8; i++)
#pragma unroll
        for (int j = 0; j < 8; j++) { acc[i][j] = 0.f; accb[i][j] = 0.f; }

    auto load_stage = [&](int s, int kk) {
#pragma unroll
        for (int u = 0; u < 2; u++) {
            int v = tid + u * 256;          // 0..511
            int rr = v >> 2;                // row in tile 0..127
            int q  = v & 3;                 // which float4 of the 16 k's
            float4 fa = *(const float4*)(t + (rowA0 + rr) * NITEM + kk + q * 4);
            As[s][q * 4 + 0][rr] = fa.x; As[s][q * 4 + 1][rr] = fa.y;
            As[s][q * 4 + 2][rr] = fa.z; As[s][q * 4 + 3][rr] = fa.w;
            float4 fb = *(const float4*)(t + (rowB0 + rr) * NITEM + kk + q * 4);
            Bs[s][q * 4 + 0][rr] = fb.x; Bs[s][q * 4 + 1][rr] = fb.y;
            Bs[s][q * 4 + 2][rr] = fb.z; Bs[s][q * 4 + 3][rr] = fb.w;
        }
    };

    load_stage(0, 0);
    __syncthreads();

    for (int kk = 0; kk < NITEM; kk += 16) {
        int s = (kk >> 4) & 1;
        if (kk + 16 < NITEM) load_stage(s ^ 1, kk + 16);
#pragma unroll
        for (int k = 0; k < 16; k++) {
            float a[8], b[8];
#pragma unroll
            for (int i = 0; i < 8; i++) a[i] = As[s][k][ty * 8 + i];
#pragma unroll
            for (int j = 0; j < 8; j++) b[j] = Bs[s][k][tx * 8 + j];
#pragma unroll
            for (int i = 0; i < 8; i++)
#pragma unroll
                for (int j = 0; j < 8; j++)
                    accb[i][j] = fmaf(a[i], b[j], accb[i][j]);
        }
        __syncthreads();

        // fold block accumulator into main every 256 k's (16 BK-blocks)
        if (((kk >> 4) & 15) == 15) {
#pragma unroll
            for (int i = 0; i < 8; i++)
#pragma unroll
                for (int j = 0; j < 8; j++) {
                    acc[i][j] += accb[i][j];
                    accb[i][j] = 0.f;
                }
        }
    }

#pragma unroll
    for (int i = 0; i < 8; i++) {
        int gi = by * 128 + ty * 8 + i;
        float invi = g_inv[gi];
#pragma unroll
        for (int j = 0; j < 8; j++) {
            int gj = bx * 128 + tx * 8 + j;
            float v = (acc[i][j] + accb[i][j]) * invi * g_inv[gj];
            if (gi == gj) v = FNEGINF;
            g_sim[(size_t)gi * NB + gj] = v;
            if (bx != by) g_sim[(size_t)gj * NB + gi] = v;
        }
    }
}

// ---------------- K4: per-row top-10 + softmax weights + gather -------------
__global__ void k_topk(const float* __restrict__ z) {
    int r = blockIdx.x;
    int tid = threadIdx.x;
    __shared__ float cv[256 * NTOPK];
    __shared__ int   ci[256 * NTOPK];
    __shared__ float tv[NTOPK];
    __shared__ int   tix[NTOPK];
    __shared__ float w[NTOPK];
    __shared__ float wsum_s;

    float lv[NTOPK]; int li[NTOPK];
#pragma unroll
    for (int k = 0; k < NTOPK; k++) { lv[k] = -FLT_MAX; li[k] = 0x7fffffff; }

    const float* row = g_sim + (size_t)r * NB;
    for (int j = tid; j < NB; j += 256) {
        float v = row[j];
        if (v > lv[NTOPK - 1] || (v == lv[NTOPK - 1] && j < li[NTOPK - 1])) {
            int p = NTOPK - 1;
            while (p > 0 && (v > lv[p - 1] || (v == lv[p - 1] && j < li[p - 1]))) {
                lv[p] = lv[p - 1]; li[p] = li[p - 1]; p--;
            }
            lv[p] = v; li[p] = j;
        }
    }
#pragma unroll
    for (int k = 0; k < NTOPK; k++) { cv[tid * NTOPK + k] = lv[k]; ci[tid * NTOPK + k] = li[k]; }
    __syncthreads();

    if (tid < 32) {
        for (int it = 0; it < NTOPK; it++) {
            float bv = -FLT_MAX; int bi = 0x7fffffff; int bp = 0;
            for (int p = tid; p < 256 * NTOPK; p += 32) {
                float v = cv[p]; int i = ci[p];
                if (v > bv || (v == bv && i < bi)) { bv = v; bi = i; bp = p; }
            }
#pragma unroll
            for (int o = 16; o; o >>= 1) {
                float ov = __shfl_down_sync(0xffffffff, bv, o);
                int   oi = __shfl_down_sync(0xffffffff, bi, o);
                int   op = __shfl_down_sync(0xffffffff, bp, o);
                if (ov > bv || (ov == bv && oi < bi)) { bv = ov; bi = oi; bp = op; }
            }
            bp = __shfl_sync(0xffffffff, bp, 0);
            if (tid == 0) { tv[it] = bv; tix[it] = bi; cv[bp] = -FLT_MAX; }
            __syncwarp();
        }
    }
    __syncthreads();

    if (tid < NTOPK) w[tid] = expf((tv[tid] - tv[0]) * (1.0f / FTEMP));
    __syncthreads();
    if (tid == 0) {
        float s = 0.f;
        for (int k = 0; k < NTOPK; k++) s += w[k];
        wsum_s = 1.0f / s;
    }
    __syncthreads();
    if (tid < NTOPK) w[tid] *= wsum_s;
    __syncthreads();

    if (tid < ND) {
        float acc = 0.f;
#pragma unroll
        for (int k = 0; k < NTOPK; k++)
            acc += w[k] * z[(size_t)tix[k] * ND + tid];
        g_nz[(size_t)r * ND + tid] = acc;
    }
}

// ---------------- K5: z_tilde + per-block loss partials ---------------------
__global__ void k_zt(const float* __restrict__ z, float* __restrict__ out) {
    int e = blockIdx.x * 256 + threadIdx.x;   // 4096 blocks * 256 = NB*ND
    int b = e >> 7;
    float a  = g_alpha[b];
    float zv = z[e];
    float nz = g_nz[e];
    float zt = (1.0f - a) * zv + a * nz;
    out[e] = zt;
    float df = zt - zv;

    __shared__ double sd[256];
    sd[threadIdx.x] = (double)df * (double)df;
    __syncthreads();
    for (int o = 128; o; o >>= 1) {
        if (threadIdx.x < o) sd[threadIdx.x] += sd[threadIdx.x + o];
        __syncthreads();
    }
    if (threadIdx.x == 0) g_part[blockIdx.x] = sd[0];
}

// ---------------- K6: final loss reduction ----------------------------------
__global__ void k_loss(float* __restrict__ out, size_t loss_idx) {
    __shared__ double sd[1024];
    double a = 0.0;
    for (int i = threadIdx.x; i < 4096; i += 1024) a += g_part[i];
    sd[threadIdx.x] = a; __syncthreads();
    for (int o = 512; o; o >>= 1) {
        if (threadIdx.x < o) sd[threadIdx.x] += sd[threadIdx.x + o];
        __syncthreads();
    }
    if (threadIdx.x == 0)
        out[loss_idx] = (float)(sd[0] / (double)((size_t)NB * ND));
}

// ---------------- launch -----------------------------------------------------
extern "C" void kernel_launch(void* const* d_in, const int* in_sizes, int n_in,
                              void* d_out, int out_size) {
    const float* z        = (const float*)d_in[0];
    const float* t        = (const float*)d_in[1];
    const int*   real_len = (const int*)d_in[2];
    const float* W1       = (const float*)d_in[3];
    const float* b1       = (const float*)d_in[4];
    const float* W2       = (const float*)d_in[5];
    const float* b2       = (const float*)d_in[6];
    float* out = (float*)d_out;

    k_maxlen<<<1, 1024>>>(real_len);
    k_alpha<<<NB / 256, 256>>>(real_len, W1, b1, W2, b2);
    k_invnorm<<<NB, 256>>>(t);

    dim3 g(NB / 128, NB / 128);
    k_gemm<<<g, 256>>>(t);

    k_topk<<<NB, 256>>>(z);
    k_zt<<<(NB * ND) / 256, 256>>>(z, out);

    // guard: only emit the scalar loss if the output buffer actually has a
    // slot beyond the flattened z_tilde (out layout = [z_tilde (NB*ND), loss])
    if (out_size > NB * ND)
        k_loss<<<1, 1024>>>(out, (size_t)out_size - 1);
}

// round 9
// speedup vs baseline: 4.1920x; 4.1920x over previous
#include <cuda_runtime.h>
#include <cuda_bf16.h>
#include <math.h>
#include <float.h>

#define NB    8192      // batch
#define ND    128       // feature dim of z
#define NITEM 16384     // interaction vector length
#define NHID  32
#define NTOPK 10
#define NCAND 16        // screening candidates per row
#define FTEMP 0.1f
#define FNEGINF -9e9f

#define BK    32        // gemm k-chunk (bf16)
#define PADB  40        // smem row stride in bf16 (80B) -> conflict-free frag loads

// ---------------- scratch (device globals; no runtime allocation) ----------
__device__ __nv_bfloat16 g_tb[(size_t)NB * NITEM];  // 256 MB bf16 copy of t
__device__ float  g_sim[(size_t)NB * NB];           // 256 MB screen similarity
__device__ float  g_inv[NB];                        // 1/row-norm of t
__device__ float  g_alpha[NB];
__device__ float  g_nz[(size_t)NB * ND];            // neighbor_z
__device__ int    g_cand[(size_t)NB * NCAND];       // screen top-16 indices
__device__ int    g_maxlen;
__device__ double g_part[4096];                     // per-block loss partials

// ---------------- K0: max(real_len) ----------------------------------------
__global__ void k_maxlen(const int* __restrict__ real_len) {
    __shared__ int s[1024];
    int tid = threadIdx.x;
    int m = 0;
    for (int i = tid; i < NB; i += 1024) m = max(m, real_len[i]);
    s[tid] = m; __syncthreads();
    for (int o = 512; o; o >>= 1) {
        if (tid < o) s[tid] = max(s[tid], s[tid + o]);
        __syncthreads();
    }
    if (tid == 0) g_maxlen = s[0];
}

// ---------------- K1: alpha[b] (tiny MLP) -----------------------------------
__global__ void k_alpha(const int* __restrict__ real_len,
                        const float* __restrict__ W1, const float* __restrict__ b1,
                        const float* __restrict__ W2, const float* __restrict__ b2) {
    int b = blockIdx.x * blockDim.x + threadIdx.x;
    if (b >= NB) return;
    float ml = fmaxf((float)g_maxlen, 1.0f);
    float sp = 1.0f - (float)real_len[b] / ml;
    float acc = 0.f;
#pragma unroll
    for (int j = 0; j < NHID; j++) {
        float h = fmaxf(sp * W1[j] + b1[j], 0.f);
        acc += h * W2[j];
    }
    acc += b2[0];
    g_alpha[b] = 1.0f / (1.0f + expf(-acc));
}

// ---------------- K2: inverse row norms of t --------------------------------
__global__ void k_invnorm(const float* __restrict__ t) {
    int r = blockIdx.x;
    __shared__ float s[256];
    const float* row = t + (size_t)r * NITEM;
    float a = 0.f;
    for (int j = threadIdx.x; j < NITEM; j += 256) { float v = row[j]; a = fmaf(v, v, a); }
    s[threadIdx.x] = a; __syncthreads();
    for (int o = 128; o; o >>= 1) {
        if (threadIdx.x < o) s[threadIdx.x] += s[threadIdx.x + o];
        __syncthreads();
    }
    if (threadIdx.x == 0) {
        float n = sqrtf(s[0]);
        g_inv[r] = 1.0f / fmaxf(n, 1e-12f);
    }
}

// ---------------- K2b: fp32 -> bf16 conversion of t -------------------------
__global__ void k_convert(const float* __restrict__ t) {
    size_t i = ((size_t)blockIdx.x * 256 + threadIdx.x) * 4;
    float4 v = *(const float4*)(t + i);
    __nv_bfloat162* dst = (__nv_bfloat162*)(g_tb + i);
    dst[0] = __nv_bfloat162(__float2bfloat16_rn(v.x), __float2bfloat16_rn(v.y));
    dst[1] = __nv_bfloat162(__float2bfloat16_rn(v.z), __float2bfloat16_rn(v.w));
}

// ---------------- K3: bf16 tensor-core screen GEMM --------------------------
// sim = (tb tb^T) * inv_i * inv_j, 128x128 tile/CTA, 8 warps (2x4), each warp
// 64x32 via mma.sync.m16n8k16 bf16->fp32. cp.async double buffer, BK=32.
// Triangular grid + mirror writes.
#define MMA16816(c, a, b) asm volatile( \
    "mma.sync.aligned.m16n8k16.row.col.f32.bf16.bf16.f32 " \
    "{%0,%1,%2,%3}, {%4,%5,%6,%7}, {%8,%9}, {%0,%1,%2,%3};" \
    : "+f"((c)[0]), "+f"((c)[1]), "+f"((c)[2]), "+f"((c)[3]) \
    : "r"((a)[0]), "r"((a)[1]), "r"((a)[2]), "r"((a)[3]), \
      "r"((b)[0]), "r"((b)[1]))

__global__ void __launch_bounds__(256) k_gemm_bf16() {
    int bx = blockIdx.x, by = blockIdx.y;
    if (bx < by) return;

    __shared__ __nv_bfloat16 As[2][128 * PADB];
    __shared__ __nv_bfloat16 Bs[2][128 * PADB];

    int tid = threadIdx.x;
    int lane = tid & 31;
    int wid = tid >> 5;
    int wm = (wid >> 2) * 64;    // warp m offset: 0 / 64
    int wn = (wid & 3) * 32;     // warp n offset: 0/32/64/96
    int lr = lane >> 2;          // 0..7
    int lk = (lane & 3) * 2;     // 0,2,4,6

    const size_t rowA0 = (size_t)by * 128;
    const size_t rowB0 = (size_t)bx * 128;

    unsigned sA[2], sB[2];
    sA[0] = (unsigned)__cvta_generic_to_shared(&As[0][0]);
    sA[1] = (unsigned)__cvta_generic_to_shared(&As[1][0]);
    sB[0] = (unsigned)__cvta_generic_to_shared(&Bs[0][0]);
    sB[1] = (unsigned)__cvta_generic_to_shared(&Bs[1][0]);

    float acc[4][4][4];
#pragma unroll
    for (int mb = 0; mb < 4; mb++)
#pragma unroll
        for (int nb = 0; nb < 4; nb++)
#pragma unroll
            for (int q = 0; q < 4; q++) acc[mb][nb][q] = 0.f;

    // stage loader: 128 rows x 32 bf16 (64B) per tile = 512 x 16B chunks/tile
    auto issue = [&](int st, int kk) {
#pragma unroll
        for (int u = 0; u < 2; u++) {
            int v = tid + u * 256;     // 0..511
            int row = v >> 2;
            int c = v & 3;             // 16B chunk within the 64B row
            unsigned soff = (unsigned)(row * PADB * 2 + c * 16);
            const __nv_bfloat16* ga = g_tb + (rowA0 + row) * (size_t)NITEM + kk + c * 8;
            asm volatile("cp.async.cg.shared.global [%0], [%1], 16;\n"
                         :: "r"(sA[st] + soff), "l"(ga));
            const __nv_bfloat16* gb = g_tb + (rowB0 + row) * (size_t)NITEM + kk + c * 8;
            asm volatile("cp.async.cg.shared.global [%0], [%1], 16;\n"
                         :: "r"(sB[st] + soff), "l"(gb));
        }
    };

    issue(0, 0);
    asm volatile("cp.async.commit_group;\n");

    int s = 0;
    for (int kk = 0; kk < NITEM; kk += BK, s ^= 1) {
        if (kk + BK < NITEM) {
            issue(s ^ 1, kk + BK);
            asm volatile("cp.async.commit_group;\n");
            asm volatile("cp.async.wait_group 1;\n");
        } else {
            asm volatile("cp.async.wait_group 0;\n");
        }
        __syncthreads();

#pragma unroll
        for (int kh = 0; kh < 2; kh++) {
            unsigned a[4][4], b[4][2];
#pragma unroll
            for (int mb = 0; mb < 4; mb++) {
                int r0 = (wm + mb * 16 + lr) * PADB + kh * 16 + lk;
                a[mb][0] = *(const unsigned*)&As[s][r0];
                a[mb][1] = *(const unsigned*)&As[s][r0 + 8 * PADB];
                a[mb][2] = *(const unsigned*)&As[s][r0 + 8];
                a[mb][3] = *(const unsigned*)&As[s][r0 + 8 * PADB + 8];
            }
#pragma unroll
            for (int nb = 0; nb < 4; nb++) {
                int c0 = (wn + nb * 8 + lr) * PADB + kh * 16 + lk;
                b[nb][0] = *(const unsigned*)&Bs[s][c0];
                b[nb][1] = *(const unsigned*)&Bs[s][c0 + 8];
            }
#pragma unroll
            for (int mb = 0; mb < 4; mb++)
#pragma unroll
                for (int nb = 0; nb < 4; nb++)
                    MMA16816(acc[mb][nb], a[mb], b[nb]);
        }
        __syncthreads();   // protect buffer s before next-iter cp.async overwrite
    }

    // epilogue: scale by inv norms, diag = -inf, mirror
#pragma unroll
    for (int mb = 0; mb < 4; mb++) {
        int gr0 = by * 128 + wm + mb * 16 + lr;
        float invr0 = g_inv[gr0];
        float invr1 = g_inv[gr0 + 8];
#pragma unroll
        for (int nb = 0; nb < 4; nb++) {
            int gc = bx * 128 + wn + nb * 8 + (lane & 3) * 2;
#pragma unroll
            for (int q = 0; q < 4; q++) {
                int gi = gr0 + ((q >> 1) ? 8 : 0);
                int gj = gc + (q & 1);
                float v = acc[mb][nb][q] * ((q >> 1) ? invr1 : invr0) * g_inv[gj];
                if (gi == gj) v = FNEGINF;
                g_sim[(size_t)gi * NB + gj] = v;
                if (bx != by) g_sim[(size_t)gj * NB + gi] = v;
            }
        }
    }
}

// ---------------- K4: per-row top-16 candidate scan (screen) ----------------
__global__ void k_topk16() {
    int r = blockIdx.x;
    int tid = threadIdx.x;
    __shared__ float cv[256 * NCAND];
    __shared__ int   ci[256 * NCAND];

    float lv[NCAND]; int li[NCAND];
#pragma unroll
    for (int k = 0; k < NCAND; k++) { lv[k] = -FLT_MAX; li[k] = 0x7fffffff; }

    const float* row = g_sim + (size_t)r * NB;
    for (int j = tid; j < NB; j += 256) {
        float v = row[j];
        if (v > lv[NCAND - 1] || (v == lv[NCAND - 1] && j < li[NCAND - 1])) {
            int p = NCAND - 1;
            while (p > 0 && (v > lv[p - 1] || (v == lv[p - 1] && j < li[p - 1]))) {
                lv[p] = lv[p - 1]; li[p] = li[p - 1]; p--;
            }
            lv[p] = v; li[p] = j;
        }
    }
#pragma unroll
    for (int k = 0; k < NCAND; k++) { cv[tid * NCAND + k] = lv[k]; ci[tid * NCAND + k] = li[k]; }
    __syncthreads();

    if (tid < 32) {
        for (int it = 0; it < NCAND; it++) {
            float bv = -FLT_MAX; int bi = 0x7fffffff; int bp = 0;
            for (int p = tid; p < 256 * NCAND; p += 32) {
                float v = cv[p]; int i = ci[p];
                if (v > bv || (v == bv && i < bi)) { bv = v; bi = i; bp = p; }
            }
#pragma unroll
            for (int o = 16; o; o >>= 1) {
                float ov = __shfl_down_sync(0xffffffff, bv, o);
                int   oi = __shfl_down_sync(0xffffffff, bi, o);
                int   op = __shfl_down_sync(0xffffffff, bp, o);
                if (ov > bv || (ov == bv && oi < bi)) { bv = ov; bi = oi; bp = op; }
            }
            bi = __shfl_sync(0xffffffff, bi, 0);
            bp = __shfl_sync(0xffffffff, bp, 0);
            if (tid == 0) { g_cand[(size_t)r * NCAND + it] = bi; cv[bp] = -FLT_MAX; }
            __syncwarp();
        }
    }
}

// ---------------- K5: exact fp32 re-rank + softmax + gather -----------------
// One block per row. 16 groups of 16 threads: group g computes exact
// dot(t_r, t_cand[g]) with component-wise accumulators + periodic fold
// (two-level accumulation, sigma ~1e-7 in sim units).
__global__ void __launch_bounds__(256) k_rerank(const float* __restrict__ t,
                                                const float* __restrict__ z) {
    int r = blockIdx.x;
    int tid = threadIdx.x;
    int grp = tid >> 4;         // candidate 0..15
    int lane16 = tid & 15;

    __shared__ float sv[NCAND];
    __shared__ int   sc[NCAND];
    __shared__ float w[NTOPK];
    __shared__ int   si[NTOPK];

    int c = g_cand[(size_t)r * NCAND + grp];
    const float4* pr = (const float4*)(t + (size_t)r * NITEM);
    const float4* pc = (const float4*)(t + (size_t)c * NITEM);

    float ax = 0.f, ay = 0.f, az = 0.f, aw = 0.f;   // inner accumulators
    float ox = 0.f, oy = 0.f, oz = 0.f, ow = 0.f;   // outer (folded)
    int it = 0;
    for (int k = lane16; k < NITEM / 4; k += 16, it++) {
        float4 a = pr[k], b = pc[k];
        ax = fmaf(a.x, b.x, ax); ay = fmaf(a.y, b.y, ay);
        az = fmaf(a.z, b.z, az); aw = fmaf(a.w, b.w, aw);
        if ((it & 63) == 63) {
            ox += ax; oy += ay; oz += az; ow += aw;
            ax = ay = az = aw = 0.f;
        }
    }
    ox += ax; oy += ay; oz += az; ow += aw;
    float sum = (ox + oy) + (oz + ow);
#pragma unroll
    for (int o = 8; o; o >>= 1)
        sum += __shfl_down_sync(0xffffffff, sum, o, 16);
    if (lane16 == 0) {
        sv[grp] = sum * g_inv[r] * g_inv[c];
        sc[grp] = c;
    }
    __syncthreads();

    if (tid == 0) {
        // insertion sort 16 candidates: value desc, index asc on ties
        float v[NCAND]; int ix[NCAND];
#pragma unroll
        for (int k = 0; k < NCAND; k++) { v[k] = sv[k]; ix[k] = sc[k]; }
        for (int i = 1; i < NCAND; i++) {
            float vv = v[i]; int vi = ix[i];
            int p = i - 1;
            while (p >= 0 && (v[p] < vv || (v[p] == vv && ix[p] > vi))) {
                v[p + 1] = v[p]; ix[p + 1] = ix[p]; p--;
            }
            v[p + 1] = vv; ix[p + 1] = vi;
        }
        float wsum = 0.f;
        float wl[NTOPK];
#pragma unroll
        for (int k = 0; k < NTOPK; k++) {
            wl[k] = expf((v[k] - v[0]) * (1.0f / FTEMP));
            wsum += wl[k];
        }
        float inv = 1.0f / wsum;
#pragma unroll
        for (int k = 0; k < NTOPK; k++) { w[k] = wl[k] * inv; si[k] = ix[k]; }
    }
    __syncthreads();

    if (tid < ND) {
        float acc = 0.f;
#pragma unroll
        for (int k = 0; k < NTOPK; k++)
            acc += w[k] * z[(size_t)si[k] * ND + tid];
        g_nz[(size_t)r * ND + tid] = acc;
    }
}

// ---------------- K6: z_tilde + per-block loss partials ---------------------
__global__ void k_zt(const float* __restrict__ z, float* __restrict__ out) {
    int e = blockIdx.x * 256 + threadIdx.x;   // 4096 blocks * 256 = NB*ND
    int b = e >> 7;
    float a  = g_alpha[b];
    float zv = z[e];
    float nz = g_nz[e];
    float zt = (1.0f - a) * zv + a * nz;
    out[e] = zt;
    float df = zt - zv;

    __shared__ double sd[256];
    sd[threadIdx.x] = (double)df * (double)df;
    __syncthreads();
    for (int o = 128; o; o >>= 1) {
        if (threadIdx.x < o) sd[threadIdx.x] += sd[threadIdx.x + o];
        __syncthreads();
    }
    if (threadIdx.x == 0) g_part[blockIdx.x] = sd[0];
}

// ---------------- K7: final loss reduction ----------------------------------
__global__ void k_loss(float* __restrict__ out, size_t loss_idx) {
    __shared__ double sd[1024];
    double a = 0.0;
    for (int i = threadIdx.x; i < 4096; i += 1024) a += g_part[i];
    sd[threadIdx.x] = a; __syncthreads();
    for (int o = 512; o; o >>= 1) {
        if (threadIdx.x < o) sd[threadIdx.x] += sd[threadIdx.x + o];
        __syncthreads();
    }
    if (threadIdx.x == 0)
        out[loss_idx] = (float)(sd[0] / (double)((size_t)NB * ND));
}

// ---------------- launch -----------------------------------------------------
extern "C" void kernel_launch(void* const* d_in, const int* in_sizes, int n_in,
                              void* d_out, int out_size) {
    const float* z        = (const float*)d_in[0];
    const float* t        = (const float*)d_in[1];
    const int*   real_len = (const int*)d_in[2];
    const float* W1       = (const float*)d_in[3];
    const float* b1       = (const float*)d_in[4];
    const float* W2       = (const float*)d_in[5];
    const float* b2       = (const float*)d_in[6];
    float* out = (float*)d_out;

    k_maxlen<<<1, 1024>>>(real_len);
    k_alpha<<<NB / 256, 256>>>(real_len, W1, b1, W2, b2);
    k_invnorm<<<NB, 256>>>(t);
    k_convert<<<(int)(((size_t)NB * NITEM / 4) / 256), 256>>>(t);

    dim3 g(NB / 128, NB / 128);
    k_gemm_bf16<<<g, 256>>>();

    k_topk16<<<NB, 256>>>();
    k_rerank<<<NB, 256>>>(t, z);
    k_zt<<<(NB * ND) / 256, 256>>>(z, out);

    if (out_size > NB * ND)
        k_loss<<<1, 1024>>>(out, (size_t)out_size - 1);
}

// round 15
// speedup vs baseline: 4.3788x; 1.0446x over previous
#include <cuda_runtime.h>
#include <cuda_bf16.h>
#include <math.h>
#include <float.h>

#define NB    8192      // batch
#define ND    128       // feature dim of z
#define NITEM 16384     // interaction vector length
#define NHID  32
#define NTOPK 10
#define NCAND 16        // screening candidates per row
#define FTEMP 0.1f
#define FNEGINF -9e9f

#define BK    64        // gemm k-chunk (bf16)
#define PADB  72        // smem row stride in bf16 (144B): 8 frag rows hit distinct banks
#define OPW   (128 * PADB)          // bf16 elems per operand stage
#define GSMEM (4 * OPW * 2)         // 2 stages x (A+B), bytes = 73728

// ---------------- scratch (device globals; no runtime allocation) ----------
__device__ __nv_bfloat16 g_tb[(size_t)NB * NITEM];  // 256 MB bf16 copy of t
__device__ float  g_sim[(size_t)NB * NB];           // 256 MB screen similarity
__device__ float  g_inv[NB];                        // 1/row-norm of t
__device__ float  g_alpha[NB];
__device__ float  g_nz[(size_t)NB * ND];            // neighbor_z
__device__ int    g_cand[(size_t)NB * NCAND];       // screen top-16 indices
__device__ int    g_maxlen;
__device__ double g_part[4096];                     // per-block loss partials

// ---------------- K0: max(real_len) ----------------------------------------
__global__ void k_maxlen(const int* __restrict__ real_len) {
    __shared__ int s[1024];
    int tid = threadIdx.x;
    int m = 0;
    for (int i = tid; i < NB; i += 1024) m = max(m, real_len[i]);
    s[tid] = m; __syncthreads();
    for (int o = 512; o; o >>= 1) {
        if (tid < o) s[tid] = max(s[tid], s[tid + o]);
        __syncthreads();
    }
    if (tid == 0) g_maxlen = s[0];
}

// ---------------- K1: alpha[b] (tiny MLP) -----------------------------------
__global__ void k_alpha(const int* __restrict__ real_len,
                        const float* __restrict__ W1, const float* __restrict__ b1,
                        const float* __restrict__ W2, const float* __restrict__ b2) {
    int b = blockIdx.x * blockDim.x + threadIdx.x;
    if (b >= NB) return;
    float ml = fmaxf((float)g_maxlen, 1.0f);
    float sp = 1.0f - (float)real_len[b] / ml;
    float acc = 0.f;
#pragma unroll
    for (int j = 0; j < NHID; j++) {
        float h = fmaxf(sp * W1[j] + b1[j], 0.f);
        acc += h * W2[j];
    }
    acc += b2[0];
    g_alpha[b] = 1.0f / (1.0f + expf(-acc));
}

// ---------------- K2: inverse row norms of t --------------------------------
__global__ void k_invnorm(const float* __restrict__ t) {
    int r = blockIdx.x;
    __shared__ float s[256];
    const float* row = t + (size_t)r * NITEM;
    float a = 0.f;
    for (int j = threadIdx.x; j < NITEM; j += 256) { float v = row[j]; a = fmaf(v, v, a); }
    s[threadIdx.x] = a; __syncthreads();
    for (int o = 128; o; o >>= 1) {
        if (threadIdx.x < o) s[threadIdx.x] += s[threadIdx.x + o];
        __syncthreads();
    }
    if (threadIdx.x == 0) {
        float n = sqrtf(s[0]);
        g_inv[r] = 1.0f / fmaxf(n, 1e-12f);
    }
}

// ---------------- K2b: fp32 -> bf16 conversion of t -------------------------
__global__ void k_convert(const float* __restrict__ t) {
    size_t i = ((size_t)blockIdx.x * 256 + threadIdx.x) * 4;
    float4 v = *(const float4*)(t + i);
    __nv_bfloat162* dst = (__nv_bfloat162*)(g_tb + i);
    dst[0] = __nv_bfloat162(__float2bfloat16_rn(v.x), __float2bfloat16_rn(v.y));
    dst[1] = __nv_bfloat162(__float2bfloat16_rn(v.z), __float2bfloat16_rn(v.w));
}

// ---------------- K3: bf16 tensor-core screen GEMM (mma.sync) ---------------
// sim = (tb tb^T) * inv_i * inv_j, 128x128 tile/CTA, 8 warps (2x4), each warp
// 64x32 via mma.sync.m16n8k16 bf16->fp32. cp.async double buffer, BK=64
// (halves barrier count vs BK=32), dynamic smem (2 CTA/SM possible),
// 8x8-supertile-swizzled triangular grid for L2 locality; mirror writes.
#define MMA16816(c, a, b) asm volatile( \
    "mma.sync.aligned.m16n8k16.row.col.f32.bf16.bf16.f32 " \
    "{%0,%1,%2,%3}, {%4,%5,%6,%7}, {%8,%9}, {%0,%1,%2,%3};" \
    : "+f"((c)[0]), "+f"((c)[1]), "+f"((c)[2]), "+f"((c)[3]) \
    : "r"((a)[0]), "r"((a)[1]), "r"((a)[2]), "r"((a)[3]), \
      "r"((b)[0]), "r"((b)[1]))

__global__ void __launch_bounds__(256) k_gemm_bf16() {
    // 8x8 supertile swizzle over the 64x64 tile grid
    int bid = blockIdx.x;
    int s6 = bid >> 6, i6 = bid & 63;
    int by = (s6 >> 3) * 8 + (i6 >> 3);
    int bx = (s6 & 7) * 8 + (i6 & 7);
    if (bx < by) return;

    extern __shared__ __nv_bfloat16 sm[];
    __nv_bfloat16* Asp[2] = { sm,           sm + OPW };
    __nv_bfloat16* Bsp[2] = { sm + 2 * OPW, sm + 3 * OPW };

    int tid = threadIdx.x;
    int lane = tid & 31;
    int wid = tid >> 5;
    int wm = (wid >> 2) * 64;    // warp m offset: 0 / 64
    int wn = (wid & 3) * 32;     // warp n offset: 0/32/64/96
    int lr = lane >> 2;          // 0..7
    int lk = (lane & 3) * 2;     // 0,2,4,6

    const size_t rowA0 = (size_t)by * 128;
    const size_t rowB0 = (size_t)bx * 128;

    unsigned sA[2], sB[2];
    sA[0] = (unsigned)__cvta_generic_to_shared(Asp[0]);
    sA[1] = (unsigned)__cvta_generic_to_shared(Asp[1]);
    sB[0] = (unsigned)__cvta_generic_to_shared(Bsp[0]);
    sB[1] = (unsigned)__cvta_generic_to_shared(Bsp[1]);

    float acc[4][4][4];
#pragma unroll
    for (int mb = 0; mb < 4; mb++)
#pragma unroll
        for (int nb = 0; nb < 4; nb++)
#pragma unroll
            for (int q = 0; q < 4; q++) acc[mb][nb][q] = 0.f;

    // stage loader: 128 rows x 64 bf16 (128B) per operand = 1024 x 16B chunks
    auto issue = [&](int st, int kk) {
#pragma unroll
        for (int u = 0; u < 4; u++) {
            int v = tid + u * 256;     // 0..1023
            int row = v >> 3;
            int c = v & 7;             // 16B chunk within the 128B row
            unsigned soff = (unsigned)(row * PADB * 2 + c * 16);
            const __nv_bfloat16* ga = g_tb + (rowA0 + row) * (size_t)NITEM + kk + c * 8;
            asm volatile("cp.async.cg.shared.global [%0], [%1], 16;\n"
                         :: "r"(sA[st] + soff), "l"(ga));
            const __nv_bfloat16* gb = g_tb + (rowB0 + row) * (size_t)NITEM + kk + c * 8;
            asm volatile("cp.async.cg.shared.global [%0], [%1], 16;\n"
                         :: "r"(sB[st] + soff), "l"(gb));
        }
    };

    issue(0, 0);
    asm volatile("cp.async.commit_group;\n");

    int s = 0;
    for (int kk = 0; kk < NITEM; kk += BK, s ^= 1) {
        if (kk + BK < NITEM) {
            issue(s ^ 1, kk + BK);
            asm volatile("cp.async.commit_group;\n");
            asm volatile("cp.async.wait_group 1;\n");
        } else {
            asm volatile("cp.async.wait_group 0;\n");
        }
        __syncthreads();

#pragma unroll
        for (int kh = 0; kh < 4; kh++) {
            unsigned a[4][4], b[4][2];
#pragma unroll
            for (int mb = 0; mb < 4; mb++) {
                int r0 = (wm + mb * 16 + lr) * PADB + kh * 16 + lk;
                a[mb][0] = *(const unsigned*)&Asp[s][r0];
                a[mb][1] = *(const unsigned*)&Asp[s][r0 + 8 * PADB];
                a[mb][2] = *(const unsigned*)&Asp[s][r0 + 8];
                a[mb][3] = *(const unsigned*)&Asp[s][r0 + 8 * PADB + 8];
            }
#pragma unroll
            for (int nb = 0; nb < 4; nb++) {
                int c0 = (wn + nb * 8 + lr) * PADB + kh * 16 + lk;
                b[nb][0] = *(const unsigned*)&Bsp[s][c0];
                b[nb][1] = *(const unsigned*)&Bsp[s][c0 + 8];
            }
#pragma unroll
            for (int mb = 0; mb < 4; mb++)
#pragma unroll
                for (int nb = 0; nb < 4; nb++)
                    MMA16816(acc[mb][nb], a[mb], b[nb]);
        }
        __syncthreads();   // protect buffer s before next-iter cp.async overwrite
    }

    // epilogue: scale by inv norms, diag = -inf, mirror
#pragma unroll
    for (int mb = 0; mb < 4; mb++) {
        int gr0 = by * 128 + wm + mb * 16 + lr;
        float invr0 = g_inv[gr0];
        float invr1 = g_inv[gr0 + 8];
#pragma unroll
        for (int nb = 0; nb < 4; nb++) {
            int gc = bx * 128 + wn + nb * 8 + (lane & 3) * 2;
#pragma unroll
            for (int q = 0; q < 4; q++) {
                int gi = gr0 + ((q >> 1) ? 8 : 0);
                int gj = gc + (q & 1);
                float v = acc[mb][nb][q] * ((q >> 1) ? invr1 : invr0) * g_inv[gj];
                if (gi == gj) v = FNEGINF;
                g_sim[(size_t)gi * NB + gj] = v;
                if (bx != by) g_sim[(size_t)gj * NB + gi] = v;
            }
        }
    }
}

// ---------------- K4: per-row top-16 candidate scan (screen) ----------------
__global__ void k_topk16() {
    int r = blockIdx.x;
    int tid = threadIdx.x;
    __shared__ float cv[256 * NCAND];
    __shared__ int   ci[256 * NCAND];

    float lv[NCAND]; int li[NCAND];
#pragma unroll
    for (int k = 0; k < NCAND; k++) { lv[k] = -FLT_MAX; li[k] = 0x7fffffff; }

    const float* row = g_sim + (size_t)r * NB;
    for (int j = tid; j < NB; j += 256) {
        float v = row[j];
        if (v > lv[NCAND - 1] || (v == lv[NCAND - 1] && j < li[NCAND - 1])) {
            int p = NCAND - 1;
            while (p > 0 && (v > lv[p - 1] || (v == lv[p - 1] && j < li[p - 1]))) {
                lv[p] = lv[p - 1]; li[p] = li[p - 1]; p--;
            }
            lv[p] = v; li[p] = j;
        }
    }
#pragma unroll
    for (int k = 0; k < NCAND; k++) { cv[tid * NCAND + k] = lv[k]; ci[tid * NCAND + k] = li[k]; }
    __syncthreads();

    if (tid < 32) {
        for (int it = 0; it < NCAND; it++) {
            float bv = -FLT_MAX; int bi = 0x7fffffff; int bp = 0;
            for (int p = tid; p < 256 * NCAND; p += 32) {
                float v = cv[p]; int i = ci[p];
                if (v > bv || (v == bv && i < bi)) { bv = v; bi = i; bp = p; }
            }
#pragma unroll
            for (int o = 16; o; o >>= 1) {
                float ov = __shfl_down_sync(0xffffffff, bv, o);
                int   oi = __shfl_down_sync(0xffffffff, bi, o);
                int   op = __shfl_down_sync(0xffffffff, bp, o);
                if (ov > bv || (ov == bv && oi < bi)) { bv = ov; bi = oi; bp = op; }
            }
            bi = __shfl_sync(0xffffffff, bi, 0);
            bp = __shfl_sync(0xffffffff, bp, 0);
            if (tid == 0) { g_cand[(size_t)r * NCAND + it] = bi; cv[bp] = -FLT_MAX; }
            __syncwarp();
        }
    }
}

// ---------------- K5: exact fp32 re-rank + softmax + gather -----------------
__global__ void __launch_bounds__(256) k_rerank(const float* __restrict__ t,
                                                const float* __restrict__ z) {
    int r = blockIdx.x;
    int tid = threadIdx.x;
    int grp = tid >> 4;         // candidate 0..15
    int lane16 = tid & 15;

    __shared__ float sv[NCAND];
    __shared__ int   sc[NCAND];
    __shared__ float w[NTOPK];
    __shared__ int   si[NTOPK];

    int c = g_cand[(size_t)r * NCAND + grp];
    const float4* pr = (const float4*)(t + (size_t)r * NITEM);
    const float4* pc = (const float4*)(t + (size_t)c * NITEM);

    float ax = 0.f, ay = 0.f, az = 0.f, aw = 0.f;   // inner accumulators
    float ox = 0.f, oy = 0.f, oz = 0.f, ow = 0.f;   // outer (folded)
    int it = 0;
    for (int k = lane16; k < NITEM / 4; k += 16, it++) {
        float4 a = pr[k], b = pc[k];
        ax = fmaf(a.x, b.x, ax); ay = fmaf(a.y, b.y, ay);
        az = fmaf(a.z, b.z, az); aw = fmaf(a.w, b.w, aw);
        if ((it & 63) == 63) {
            ox += ax; oy += ay; oz += az; ow += aw;
            ax = ay = az = aw = 0.f;
        }
    }
    ox += ax; oy += ay; oz += az; ow += aw;
    float sum = (ox + oy) + (oz + ow);
#pragma unroll
    for (int o = 8; o; o >>= 1)
        sum += __shfl_down_sync(0xffffffff, sum, o, 16);
    if (lane16 == 0) {
        sv[grp] = sum * g_inv[r] * g_inv[c];
        sc[grp] = c;
    }
    __syncthreads();

    if (tid == 0) {
        float v[NCAND]; int ix[NCAND];
#pragma unroll
        for (int k = 0; k < NCAND; k++) { v[k] = sv[k]; ix[k] = sc[k]; }
        for (int i = 1; i < NCAND; i++) {
            float vv = v[i]; int vi = ix[i];
            int p = i - 1;
            while (p >= 0 && (v[p] < vv || (v[p] == vv && ix[p] > vi))) {
                v[p + 1] = v[p]; ix[p + 1] = ix[p]; p--;
            }
            v[p + 1] = vv; ix[p + 1] = vi;
        }
        float wsum = 0.f;
        float wl[NTOPK];
#pragma unroll
        for (int k = 0; k < NTOPK; k++) {
            wl[k] = expf((v[k] - v[0]) * (1.0f / FTEMP));
            wsum += wl[k];
        }
        float inv = 1.0f / wsum;
#pragma unroll
        for (int k = 0; k < NTOPK; k++) { w[k] = wl[k] * inv; si[k] = ix[k]; }
    }
    __syncthreads();

    if (tid < ND) {
        float acc = 0.f;
#pragma unroll
        for (int k = 0; k < NTOPK; k++)
            acc += w[k] * z[(size_t)si[k] * ND + tid];
        g_nz[(size_t)r * ND + tid] = acc;
    }
}

// ---------------- K6: z_tilde + per-block loss partials ---------------------
__global__ void k_zt(const float* __restrict__ z, float* __restrict__ out) {
    int e = blockIdx.x * 256 + threadIdx.x;
    int b = e >> 7;
    float a  = g_alpha[b];
    float zv = z[e];
    float nz = g_nz[e];
    float zt = (1.0f - a) * zv + a * nz;
    out[e] = zt;
    float df = zt - zv;

    __shared__ double sd[256];
    sd[threadIdx.x] = (double)df * (double)df;
    __syncthreads();
    for (int o = 128; o; o >>= 1) {
        if (threadIdx.x < o) sd[threadIdx.x] += sd[threadIdx.x + o];
        __syncthreads();
    }
    if (threadIdx.x == 0) g_part[blockIdx.x] = sd[0];
}

// ---------------- K7: final loss reduction ----------------------------------
__global__ void k_loss(float* __restrict__ out, size_t loss_idx) {
    __shared__ double sd[1024];
    double a = 0.0;
    for (int i = threadIdx.x; i < 4096; i += 1024) a += g_part[i];
    sd[threadIdx.x] = a; __syncthreads();
    for (int o = 512; o; o >>= 1) {
        if (threadIdx.x < o) sd[threadIdx.x] += sd[threadIdx.x + o];
        __syncthreads();
    }
    if (threadIdx.x == 0)
        out[loss_idx] = (float)(sd[0] / (double)((size_t)NB * ND));
}

// ---------------- launch -----------------------------------------------------
extern "C" void kernel_launch(void* const* d_in, const int* in_sizes, int n_in,
                              void* d_out, int out_size) {
    const float* z        = (const float*)d_in[0];
    const float* t        = (const float*)d_in[1];
    const int*   real_len = (const int*)d_in[2];
    const float* W1       = (const float*)d_in[3];
    const float* b1       = (const float*)d_in[4];
    const float* W2       = (const float*)d_in[5];
    const float* b2       = (const float*)d_in[6];
    float* out = (float*)d_out;

    k_maxlen<<<1, 1024>>>(real_len);
    k_alpha<<<NB / 256, 256>>>(real_len, W1, b1, W2, b2);
    k_invnorm<<<NB, 256>>>(t);
    k_convert<<<(int)(((size_t)NB * NITEM / 4) / 256), 256>>>(t);

    // idempotent host-side attribute set; no allocation; graph-capture legal
    cudaFuncSetAttribute(k_gemm_bf16, cudaFuncAttributeMaxDynamicSharedMemorySize,
                         GSMEM);
    k_gemm_bf16<<<4096, 256, GSMEM>>>();

    k_topk16<<<NB, 256>>>();
    k_rerank<<<NB, 256>>>(t, z);
    k_zt<<<(NB * ND) / 256, 256>>>(z, out);

    if (out_size > NB * ND)
        k_loss<<<1, 1024>>>(out, (size_t)out_size - 1);
}